// round 2
// baseline (speedup 1.0000x reference)
#include <cuda_runtime.h>
#include <cstdint>

// Problem constants
#define M_Q 65536
#define N_K 65536
#define KNB 16
#define CH  64
#define WST 68   // padded row stride for transposed weight tiles (conflict-free LDS.128)

// ---------------------------------------------------------------------------
// Device-global scratch (allocation-free workaround per harness rules)
// ---------------------------------------------------------------------------
__device__ float g_A [CH * CH];        // A = Wqk @ Wg1
__device__ float g_QG[M_Q * CH];       // (q+q_pos)@A + bg1
__device__ float g_KG[N_K * CH];       // (k+k_pos)@A
__device__ int   g_mask_mode;          // 0 = uint8, 1 = int32, 2 = float32

// ---------------------------------------------------------------------------
// Packed fp32x2 helpers (sm_103a FFMA2 path — ptxas won't auto-fuse)
// ---------------------------------------------------------------------------
__device__ __forceinline__ unsigned long long fma2(unsigned long long a,
                                                   unsigned long long b,
                                                   unsigned long long c) {
    unsigned long long d;
    asm("fma.rn.f32x2 %0, %1, %2, %3;" : "=l"(d) : "l"(a), "l"(b), "l"(c));
    return d;
}
__device__ __forceinline__ float hsum2(unsigned long long v) {
    float lo, hi;
    asm("mov.b64 {%0, %1}, %2;" : "=f"(lo), "=f"(hi) : "l"(v));
    return lo + hi;
}

// ---------------------------------------------------------------------------
// Kernel 0: detect mask dtype by scanning the first M*K bytes (safe for all
// candidate dtypes). Single block; writes g_mask_mode.
//   float32 "true" (1.0f) -> byte 0x3f at offset%4==3  (impossible for 0/1
//   bool/int payloads)
//   uint8 bool -> nonzero bytes appear at offsets%4 != 0
//   int32 0/1 -> nonzero only at offsets%4 == 0
// ---------------------------------------------------------------------------
__global__ void detect_mask_kernel(const unsigned char* __restrict__ mask) {
    __shared__ int sA, sB;   // sA: f32 signature, sB: nonzero at non-word offset
    int tid = threadIdx.x;
    if (tid == 0) { sA = 0; sB = 0; }
    __syncthreads();

    const int total = M_Q * KNB;          // 1 MiB of bytes, 16B-aligned buffer
    const uint4* p = (const uint4*)mask;
    int nvec = total / 16;
    int fA = 0, fB = 0;
    for (int i = tid; i < nvec; i += blockDim.x) {
        uint4 v = p[i];
        unsigned w[4] = {v.x, v.y, v.z, v.w};
#pragma unroll
        for (int j = 0; j < 4; j++) {
            if ((w[j] >> 24) == 0x3fu) fA = 1;           // byte at %4==3
            if (w[j] & 0x00ffff00u)    fB = 1;           // bytes at %4==1,2
            if ((w[j] >> 24) && ((w[j] >> 24) != 0x3fu)) fB = 1; // byte %4==3 nonzero, non-f32
        }
    }
    if (fA) atomicOr(&sA, 1);
    if (fB) atomicOr(&sB, 1);
    __syncthreads();
    if (tid == 0) {
        g_mask_mode = sA ? 2 : (sB ? 0 : 1);
    }
}

// ---------------------------------------------------------------------------
// Kernel 1: A = Wqk @ Wg1   (64x64, trivial)
// ---------------------------------------------------------------------------
__global__ void compute_A_kernel(const float* __restrict__ Wqk,
                                 const float* __restrict__ Wg1) {
    int t = blockIdx.x * blockDim.x + threadIdx.x;   // 0..4095
    int r = t >> 6, c = t & 63;
    float s = 0.f;
#pragma unroll
    for (int u = 0; u < CH; u++) s += Wqk[r * CH + u] * Wg1[u * CH + c];
    g_A[t] = s;
}

// ---------------------------------------------------------------------------
// Kernel 2: row projection  dst[r] = (src[r]+pos[r]) @ A (+ bias)
// ---------------------------------------------------------------------------
__global__ __launch_bounds__(256) void project_kernel(
    const float* __restrict__ src, const float* __restrict__ pos,
    const float* __restrict__ bias, int dst_sel, int nrows)
{
    __shared__ __align__(16) float AT[CH * WST];
    __shared__ __align__(16) float rowbuf[8][4][CH];
    __shared__ float bsh[CH];

    int tid = threadIdx.x, lane = tid & 31, wid = tid >> 5;
    float* dst = dst_sel ? g_KG : g_QG;

    for (int i = tid; i < CH * CH; i += 256) {
        int t = i >> 6, c = i & 63;
        AT[c * WST + t] = g_A[i];
    }
    if (tid < CH) bsh[tid] = bias ? bias[tid] : 0.f;
    __syncthreads();

    int base = (blockIdx.x * 8 + wid) * 4;
    if (base >= nrows) return;

    float* rb = &rowbuf[wid][0][0];
#pragma unroll
    for (int j = 0; j < 4; j++) {
        int r = base + j;
        rb[j * CH + lane]      = src[r * CH + lane]      + pos[r * CH + lane];
        rb[j * CH + 32 + lane] = src[r * CH + 32 + lane] + pos[r * CH + 32 + lane];
    }
    __syncwarp();

    unsigned long long accA[4] = {0ull, 0ull, 0ull, 0ull};
    unsigned long long accB[4] = {0ull, 0ull, 0ull, 0ull};
    const float* wr0 = AT + lane * WST;
    const float* wr1 = AT + (lane + 32) * WST;

#pragma unroll
    for (int t4 = 0; t4 < CH; t4 += 4) {
        ulonglong2 wa = *reinterpret_cast<const ulonglong2*>(wr0 + t4);
        ulonglong2 wb = *reinterpret_cast<const ulonglong2*>(wr1 + t4);
#pragma unroll
        for (int j = 0; j < 4; j++) {
            ulonglong2 hp = *reinterpret_cast<const ulonglong2*>(rb + j * CH + t4);
            accA[j] = fma2(hp.x, wa.x, accA[j]);
            accA[j] = fma2(hp.y, wa.y, accA[j]);
            accB[j] = fma2(hp.x, wb.x, accB[j]);
            accB[j] = fma2(hp.y, wb.y, accB[j]);
        }
    }
#pragma unroll
    for (int j = 0; j < 4; j++) {
        int r = base + j;
        dst[r * CH + lane]      = hsum2(accA[j]) + bsh[lane];
        dst[r * CH + 32 + lane] = hsum2(accB[j]) + bsh[lane + 32];
    }
}

// ---------------------------------------------------------------------------
// Kernel 3: fused main attention. One warp = one query.
// ---------------------------------------------------------------------------
#define SMEM_FLOATS (3 * CH * WST + 3 * CH + 4 * KNB * CH)
#define SMEM_BYTES  (SMEM_FLOATS * 4)

__global__ __launch_bounds__(128) void attn_kernel(
    const float* __restrict__ value, const unsigned char* __restrict__ mask,
    const int* __restrict__ knn,
    const float* __restrict__ Wg2, const float* __restrict__ bg2,
    const float* __restrict__ Wv,  const float* __restrict__ bv,
    const float* __restrict__ Wt,  const float* __restrict__ bt,
    float* __restrict__ out)
{
    extern __shared__ __align__(16) float sm[];
    float* w2t = sm;                       // [64][WST]
    float* wvt = w2t + CH * WST;
    float* wtt = wvt + CH * WST;
    float* bsh = wtt + CH * WST;           // bg2 | bv | bt
    float* hb  = bsh + 3 * CH;             // 4 warps x [16][64]

    int tid = threadIdx.x, lane = tid & 31, wid = tid >> 5;

    for (int i = tid; i < CH * CH; i += 128) {
        int c = i >> 6, f = i & 63;
        w2t[f * WST + c] = Wg2[i];
        wvt[f * WST + c] = Wv[i];
        wtt[f * WST + c] = Wt[i];
    }
    if (tid < CH) {
        bsh[tid]          = bg2[tid];
        bsh[CH + tid]     = bv[tid];
        bsh[2 * CH + tid] = bt[tid];
    }
    __syncthreads();

    int m = blockIdx.x * 4 + wid;
    float* h = hb + wid * (KNB * CH);

    // preload neighbor ids + mask into lanes 0..15, distribute via shfl
    int nb = 0, mk = 0;
    int mmode = g_mask_mode;
    if (lane < KNB) {
        size_t ix = (size_t)m * KNB + lane;
        nb = knn[(size_t)M_Q * KNB + ix];            // row 1 of knearest_idx
        if (mmode == 0)      mk = mask[ix] != 0;
        else if (mmode == 1) mk = ((const int*)mask)[ix] != 0;
        else                 mk = ((const float*)mask)[ix] != 0.f;
    }

    float qg0 = g_QG[m * CH + lane];
    float qg1 = g_QG[m * CH + 32 + lane];

    // ---- Phase A: gather + relu-diff into shared ----
#pragma unroll
    for (int e = 0; e < KNB; e++) {
        int n = __shfl_sync(0xffffffffu, nb, e);
        float k0 = g_KG[n * CH + lane];
        float k1 = g_KG[n * CH + 32 + lane];
        h[e * CH + lane]      = fmaxf(qg0 - k0, 0.f);
        h[e * CH + 32 + lane] = fmaxf(qg1 - k1, 0.f);
    }
    __syncwarp();

    // ---- Phase B: logits = h @ Wg2 ----
    unsigned long long accA[KNB], accB[KNB];
#pragma unroll
    for (int e = 0; e < KNB; e++) { accA[e] = 0ull; accB[e] = 0ull; }
    {
        const float* r0 = w2t + lane * WST;
        const float* r1 = w2t + (lane + 32) * WST;
        for (int c4 = 0; c4 < CH; c4 += 4) {
            ulonglong2 wa = *reinterpret_cast<const ulonglong2*>(r0 + c4);
            ulonglong2 wb = *reinterpret_cast<const ulonglong2*>(r1 + c4);
#pragma unroll
            for (int e = 0; e < KNB; e++) {
                ulonglong2 hp = *reinterpret_cast<const ulonglong2*>(h + e * CH + c4);
                accA[e] = fma2(hp.x, wa.x, accA[e]);
                accA[e] = fma2(hp.y, wa.y, accA[e]);
                accB[e] = fma2(hp.x, wb.x, accB[e]);
                accB[e] = fma2(hp.y, wb.y, accB[e]);
            }
        }
    }

    // ---- mask + softmax over neighbors (per channel) ----
    float p0[KNB], p1[KNB];
    float b0 = bsh[lane], b1 = bsh[32 + lane];
    float mx0 = -3.4e38f, mx1 = -3.4e38f;
#pragma unroll
    for (int e = 0; e < KNB; e++) {
        int mm = __shfl_sync(0xffffffffu, mk, e);
        float e0 = hsum2(accA[e]) + b0;
        float e1 = hsum2(accB[e]) + b1;
        if (mm) { e0 = -1e12f; e1 = -1e12f; }
        p0[e] = e0; p1[e] = e1;
        mx0 = fmaxf(mx0, e0); mx1 = fmaxf(mx1, e1);
    }
    float s0 = 0.f, s1 = 0.f;
#pragma unroll
    for (int e = 0; e < KNB; e++) {
        p0[e] = __expf(p0[e] - mx0); s0 += p0[e];
        p1[e] = __expf(p1[e] - mx1); s1 += p1[e];
    }
    float inv0 = 1.f / s0, inv1 = 1.f / s1;

    // ---- Phase C: v = value @ Wv, weighted aggregate ----
    __syncwarp();
    const float* vs = value + (size_t)m * KNB * CH;
#pragma unroll
    for (int e = 0; e < KNB; e++) {
        h[e * CH + lane]      = vs[e * CH + lane];
        h[e * CH + 32 + lane] = vs[e * CH + 32 + lane];
    }
    __syncwarp();

#pragma unroll
    for (int e = 0; e < KNB; e++) { accA[e] = 0ull; accB[e] = 0ull; }
    {
        const float* r0 = wvt + lane * WST;
        const float* r1 = wvt + (lane + 32) * WST;
        for (int c4 = 0; c4 < CH; c4 += 4) {
            ulonglong2 wa = *reinterpret_cast<const ulonglong2*>(r0 + c4);
            ulonglong2 wb = *reinterpret_cast<const ulonglong2*>(r1 + c4);
#pragma unroll
            for (int e = 0; e < KNB; e++) {
                ulonglong2 hp = *reinterpret_cast<const ulonglong2*>(h + e * CH + c4);
                accA[e] = fma2(hp.x, wa.x, accA[e]);
                accA[e] = fma2(hp.y, wa.y, accA[e]);
                accB[e] = fma2(hp.x, wb.x, accB[e]);
                accB[e] = fma2(hp.y, wb.y, accB[e]);
            }
        }
    }
    float bv0 = bsh[CH + lane], bv1 = bsh[CH + 32 + lane];
    float res0 = 0.f, res1 = 0.f;
#pragma unroll
    for (int e = 0; e < KNB; e++) {
        res0 += p0[e] * (hsum2(accA[e]) + bv0);
        res1 += p1[e] * (hsum2(accB[e]) + bv1);
    }
    res0 *= inv0; res1 *= inv1;

    // ---- Phase D: out = res @ Wt + bt ----
    __syncwarp();
    h[lane] = res0; h[32 + lane] = res1;
    __syncwarp();

    unsigned long long dA = 0ull, dB = 0ull;
    {
        const float* r0 = wtt + lane * WST;
        const float* r1 = wtt + (lane + 32) * WST;
#pragma unroll
        for (int c4 = 0; c4 < CH; c4 += 4) {
            ulonglong2 wa = *reinterpret_cast<const ulonglong2*>(r0 + c4);
            ulonglong2 wb = *reinterpret_cast<const ulonglong2*>(r1 + c4);
            ulonglong2 hp = *reinterpret_cast<const ulonglong2*>(h + c4);
            dA = fma2(hp.x, wa.x, dA);
            dA = fma2(hp.y, wa.y, dA);
            dB = fma2(hp.x, wb.x, dB);
            dB = fma2(hp.y, wb.y, dB);
        }
    }
    out[(size_t)m * CH + lane]      = hsum2(dA) + bsh[2 * CH + lane];
    out[(size_t)m * CH + 32 + lane] = hsum2(dB) + bsh[2 * CH + 32 + lane];
}

// ---------------------------------------------------------------------------
// kernel_launch
// Inputs (metadata order):
//  0 q, 1 k, 2 value, 3 q_pos, 4 k_pos, 5 mask(bool), 6 knearest_idx(i32),
//  7 k_num(i32), 8 Wqk, 9 bqk, 10 Wv, 11 bv, 12 Wg1, 13 bg1, 14 Wg2, 15 bg2,
//  16 Wt, 17 bt.   Output: [M, C] f32.
// ---------------------------------------------------------------------------
extern "C" void kernel_launch(void* const* d_in, const int* in_sizes, int n_in,
                              void* d_out, int out_size)
{
    const float* q      = (const float*)d_in[0];
    const float* k      = (const float*)d_in[1];
    const float* value  = (const float*)d_in[2];
    const float* q_pos  = (const float*)d_in[3];
    const float* k_pos  = (const float*)d_in[4];
    const unsigned char* mask = (const unsigned char*)d_in[5];
    const int*   knn    = (const int*)d_in[6];
    const float* Wqk    = (const float*)d_in[8];
    const float* Wv     = (const float*)d_in[10];
    const float* bv     = (const float*)d_in[11];
    const float* Wg1    = (const float*)d_in[12];
    const float* bg1    = (const float*)d_in[13];
    const float* Wg2    = (const float*)d_in[14];
    const float* bg2    = (const float*)d_in[15];
    const float* Wt     = (const float*)d_in[16];
    const float* bt     = (const float*)d_in[17];
    float* out = (float*)d_out;

    cudaFuncSetAttribute(attn_kernel,
                         cudaFuncAttributeMaxDynamicSharedMemorySize, SMEM_BYTES);

    detect_mask_kernel<<<1, 1024>>>(mask);
    compute_A_kernel<<<8, 512>>>(Wqk, Wg1);
    project_kernel<<<M_Q / 32, 256>>>(q, q_pos, bg1, /*dst_sel=*/0, M_Q);
    project_kernel<<<N_K / 32, 256>>>(k, k_pos, nullptr, /*dst_sel=*/1, N_K);
    attn_kernel<<<M_Q / 4, 128, SMEM_BYTES>>>(value, mask, knn,
                                              Wg2, bg2, Wv, bv, Wt, bt, out);
}